// round 3
// baseline (speedup 1.0000x reference)
#include <cuda_runtime.h>
#include <cuda_bf16.h>
#include <cstdint>

// Problem constants (fixed by the dataset)
#define B 64
#define S 8192
#define C 48
#define L 42
#define LP1 (L + 1)          // 43
#define IGNORE_LBL (-100)

#define ROW_THREADS 1024
#define ROW_WARPS   (ROW_THREADS / 32)   // 32
#define NCH   4                          // chunks per row
#define CHUNK (S / NCH)                  // 2048
#define SUBS  (CHUNK / ROW_THREADS)      // 2 positions per thread
#define NSEG  (SUBS * ROW_WARPS)         // 64 warp-segments per chunk
#define NCHT  (B * NCH)                  // 256 total chunks

// ---------------------------------------------------------------------------
// Device-global scratch (no allocations allowed)
// ---------------------------------------------------------------------------
__device__ double g_partial[NCHT];   // per-chunk score partial (emis + intra trans)
__device__ int    g_pcount[NCHT];    // per-chunk valid-token count
__device__ int    g_first[NCHT];     // per-chunk first valid label (-1 if none)
__device__ int    g_last[NCHT];      // per-chunk last valid label  (-1 if none)
__device__ unsigned g_ticket;        // finish counter (reset by last block)

// ---------------------------------------------------------------------------
// One block per (row, chunk). 256 blocks total = 1 full wave.
// ---------------------------------------------------------------------------
__global__ __launch_bounds__(ROW_THREADS)
void crf_fused_kernel(const float* __restrict__ log_probs,
                      const float* __restrict__ A_scores,
                      const int*   __restrict__ labels,
                      float*       __restrict__ out) {
    const int cid  = blockIdx.x;        // chunk id
    const int b    = cid / NCH;         // batch row
    const int ch   = cid % NCH;         // chunk within row
    const int tid  = threadIdx.x;
    const int lane = tid & 31;
    const int wid  = tid >> 5;

    __shared__ float  A_sh[L + L * LP1];   // 1848 raw scores
    __shared__ float  lse_sh[LP1];
    __shared__ float  trans_sh[L * L];
    __shared__ float  start_sh[L];
    __shared__ float  fin_sh[L];
    __shared__ int    seg_first[NSEG];
    __shared__ int    seg_last[NSEG];
    __shared__ double red[ROW_WARPS];
    __shared__ int    redc[ROW_WARPS];
    __shared__ int    is_last;
    __shared__ double row_sum[B];
    __shared__ int    row_cnt[B];

    // ---- 1. stage A_scores into shared; issue label loads (in flight) ----
    #pragma unroll
    for (int i = tid; i < L + L * LP1; i += ROW_THREADS) A_sh[i] = A_scores[i];

    const int* lab = labels + (size_t)b * S + (size_t)ch * CHUNK;
    int ys[SUBS];
    #pragma unroll
    for (int i = 0; i < SUBS; i++) ys[i] = __ldg(lab + i * ROW_THREADS + tid);

    __syncthreads();   // A_sh ready

    // ---- 2. per-row log-sum-exp (warp w handles rows w, w+32) ----
    #pragma unroll
    for (int rr = 0; rr < 2; rr++) {
        int r = wid + rr * ROW_WARPS;
        if (r <= L) {
            int n = (r == L) ? L : LP1;
            const float* row = (r == L) ? A_sh : (A_sh + L + r * LP1);
            float v0 = (lane < n)      ? row[lane]      : -1e30f;
            float v1 = (lane + 32 < n) ? row[lane + 32] : -1e30f;
            float m = fmaxf(v0, v1);
            #pragma unroll
            for (int o = 16; o > 0; o >>= 1)
                m = fmaxf(m, __shfl_xor_sync(0xffffffffu, m, o));
            float s = ((lane < n) ? __expf(v0 - m) : 0.f)
                    + ((lane + 32 < n) ? __expf(v1 - m) : 0.f);
            #pragma unroll
            for (int o = 16; o > 0; o >>= 1)
                s += __shfl_xor_sync(0xffffffffu, s, o);
            if (lane == 0) lse_sh[r] = m + __logf(s);
        }
    }
    __syncthreads();

    // ---- 3. normalized tables ----
    #pragma unroll
    for (int i = tid; i < L * L; i += ROW_THREADS) {
        int r = i / L, c = i % L;
        trans_sh[i] = A_sh[L + r * LP1 + c] - lse_sh[r];
    }
    if (tid < L) {
        start_sh[tid] = A_sh[tid] - lse_sh[L];
        fin_sh[tid]   = A_sh[L + tid * LP1 + L] - lse_sh[tid];
    }
    __syncthreads();

    // ---- 4. emission gathers (order-independent), both in flight ----
    const float* lpb = log_probs + (size_t)b * S * C + (size_t)ch * CHUNK * C;
    float emis[SUBS];
    #pragma unroll
    for (int i = 0; i < SUBS; i++) {
        int p = i * ROW_THREADS + tid;
        emis[i] = (ys[i] != IGNORE_LBL) ? __ldg(lpb + (size_t)p * C + ys[i]) : 0.0f;
    }

    double local = 0.0;
    int    cnt   = 0;
    #pragma unroll
    for (int i = 0; i < SUBS; i++) {
        local += (double)emis[i];
        cnt   += (ys[i] != IGNORE_LBL) ? 1 : 0;
    }

    // ---- 5. intra-warp transitions + warp-segment endpoints ----
    // Sub-chunk i covers positions [i*1024, (i+1)*1024); segment = i*32 + wid.
    #pragma unroll
    for (int i = 0; i < SUBS; i++) {
        int y = ys[i];
        bool valid = (y != IGNORE_LBL);
        unsigned m = __ballot_sync(0xffffffffu, valid);
        unsigned rest = m & (0xFFFFFFFEu << lane);  // valid lanes strictly after me
        int partner = rest ? (__ffs(rest) - 1) : -1;
        int ynext = __shfl_sync(0xffffffffu, y, partner & 31);
        if (valid && partner >= 0)
            local += (double)trans_sh[(y - 1) * L + (ynext - 1)];

        int firstlane = __ffs(m) - 1;        // -1 if empty
        int lastlane  = 31 - __clz(m | 1u);  // garbage if empty (guarded below)
        int yf = __shfl_sync(0xffffffffu, y, firstlane & 31);
        int yl = __shfl_sync(0xffffffffu, y, lastlane & 31);
        if (lane == 0) {
            int seg = i * ROW_WARPS + wid;
            seg_first[seg] = m ? yf : -1;
            seg_last[seg]  = m ? yl : -1;
        }
    }
    __syncthreads();

    // ---- 6. chain the 64 warp-segments (thread 0) ----
    if (tid == 0) {
        double bsum = 0.0;
        int prev = -1, bf = -1;
        #pragma unroll 4
        for (int s2 = 0; s2 < NSEG; s2++) {
            int f = seg_first[s2];
            if (f < 0) continue;
            if (prev >= 0) bsum += (double)trans_sh[(prev - 1) * L + (f - 1)];
            else           bf = f;
            prev = seg_last[s2];
        }
        local += bsum;
        g_first[cid] = bf;
        g_last[cid]  = prev;
    }

    // ---- 7. block reduction (double + int) ----
    #pragma unroll
    for (int o = 16; o > 0; o >>= 1) {
        local += __shfl_down_sync(0xffffffffu, local, o);
        cnt   += __shfl_down_sync(0xffffffffu, cnt, o);
    }
    if (lane == 0) { red[wid] = local; redc[wid] = cnt; }
    __syncthreads();
    if (wid == 0) {
        double v = red[lane];
        int    c = redc[lane];
        #pragma unroll
        for (int o = 16; o > 0; o >>= 1) {
            v += __shfl_down_sync(0xffffffffu, v, o);
            c += __shfl_down_sync(0xffffffffu, c, o);
        }
        if (lane == 0) {
            g_partial[cid] = v;
            g_pcount[cid]  = c;
            __threadfence();
            unsigned t = atomicAdd(&g_ticket, 1u);
            is_last = (t == NCHT - 1) ? 1 : 0;
        }
    }
    __syncthreads();

    // ---- 8. last block: stitch chunk boundaries + start/final, finalize ----
    if (is_last) {
        if (tid < B) {
            double s = 0.0; int c = 0, prev = -1, f0 = -1;
            #pragma unroll
            for (int k = 0; k < NCH; k++) {
                int idx = tid * NCH + k;
                s += g_partial[idx];
                c += g_pcount[idx];
                int f = g_first[idx];
                if (f >= 0) {
                    if (prev >= 0) s += (double)trans_sh[(prev - 1) * L + (f - 1)];
                    else           f0 = f;
                    prev = g_last[idx];
                }
            }
            if (f0 >= 0) s += (double)start_sh[f0 - 1] + (double)fin_sh[prev - 1];
            row_sum[tid] = s;
            row_cnt[tid] = c;
        }
        __syncthreads();
        if (wid == 0) {
            double s = row_sum[lane] + row_sum[lane + 32];
            int    c = row_cnt[lane] + row_cnt[lane + 32];
            #pragma unroll
            for (int o = 16; o > 0; o >>= 1) {
                s += __shfl_down_sync(0xffffffffu, s, o);
                c += __shfl_down_sync(0xffffffffu, c, o);
            }
            if (lane == 0) {
                out[0] = (float)(s / (double)c);
                g_ticket = 0;    // reset for graph replay
            }
        }
    }
}

// ---------------------------------------------------------------------------
// Launch
// ---------------------------------------------------------------------------
extern "C" void kernel_launch(void* const* d_in, const int* in_sizes, int n_in,
                              void* d_out, int out_size) {
    const float* log_probs = (const float*)d_in[0];   // (B, S, C) f32
    const float* A_scores  = (const float*)d_in[1];   // (N_ARCS,) f32
    const int*   labels    = (const int*)d_in[2];     // (B, S) i32
    float* out = (float*)d_out;

    crf_fused_kernel<<<NCHT, ROW_THREADS>>>(log_probs, A_scores, labels, out);
}

// round 4
// speedup vs baseline: 1.1719x; 1.1719x over previous
#include <cuda_runtime.h>
#include <cuda_bf16.h>
#include <cstdint>

// Problem constants (fixed by the dataset)
#define B 64
#define S 8192
#define C 48
#define L 42
#define LP1 (L + 1)          // 43
#define IGNORE_LBL (-100)

#define ROW_THREADS 1024
#define ROW_WARPS   (ROW_THREADS / 32)   // 32
#define NCH   4                          // chunks per row
#define CHUNK (S / NCH)                  // 2048
#define SUBS  (CHUNK / ROW_THREADS)      // 2 positions per thread
#define NSEG  (SUBS * ROW_WARPS)         // 64 warp-segments per chunk
#define NCHT  (B * NCH)                  // 256 total chunks

// ---------------------------------------------------------------------------
// Device-global scratch (no allocations allowed)
// ---------------------------------------------------------------------------
__device__ double g_partial[NCHT];   // per-chunk score partial
__device__ int    g_pcount[NCHT];    // per-chunk valid-token count
__device__ int    g_first[NCHT];     // per-chunk first valid label (-1 if none)
__device__ int    g_last[NCHT];      // per-chunk last valid label  (-1 if none)
__device__ unsigned g_ticket;        // finish counter (reset by last block)

// ---------------------------------------------------------------------------
// One block per (row, chunk). 256 blocks = 1 full wave at 2 blocks/SM.
// NOTE: log_probs deliberately NOT const __restrict__ — we do not want the
// nc/texture load path (full-line DRAM promotion) for the scattered gather.
// ---------------------------------------------------------------------------
__global__ __launch_bounds__(ROW_THREADS)
void crf_fused_kernel(const float* log_probs,
                      const float* __restrict__ A_scores,
                      const int*   __restrict__ labels,
                      float*       __restrict__ out) {
    const int cid  = blockIdx.x;        // chunk id
    const int b    = cid / NCH;         // batch row
    const int ch   = cid % NCH;         // chunk within row
    const int tid  = threadIdx.x;
    const int lane = tid & 31;
    const int wid  = tid >> 5;

    __shared__ float    A_sh[L + L * LP1];   // 1848 raw scores
    __shared__ float    lse_sh[LP1];
    __shared__ float    trans_sh[L * L];
    __shared__ float    start_sh[L];
    __shared__ float    fin_sh[L];
    __shared__ int      seg_first[NSEG];
    __shared__ int      seg_last[NSEG];
    __shared__ unsigned seg_mask[2];
    __shared__ double   red[ROW_WARPS];
    __shared__ int      redc[ROW_WARPS];
    __shared__ int      is_last;
    __shared__ double   row_sum[B];
    __shared__ int      row_cnt[B];

    // ---- 1. stage A_scores into shared; issue label loads (in flight) ----
    #pragma unroll
    for (int i = tid; i < L + L * LP1; i += ROW_THREADS) A_sh[i] = A_scores[i];

    const int* lab = labels + (size_t)b * S + (size_t)ch * CHUNK;
    int ys[SUBS];
    #pragma unroll
    for (int i = 0; i < SUBS; i++) ys[i] = __ldg(lab + i * ROW_THREADS + tid);

    __syncthreads();   // A_sh ready (label LDGs still in flight)

    // ---- 2. per-row log-sum-exp (warp w handles rows w, w+32) ----
    #pragma unroll
    for (int rr = 0; rr < 2; rr++) {
        int r = wid + rr * ROW_WARPS;
        if (r <= L) {
            int n = (r == L) ? L : LP1;
            const float* row = (r == L) ? A_sh : (A_sh + L + r * LP1);
            float v0 = (lane < n)      ? row[lane]      : -1e30f;
            float v1 = (lane + 32 < n) ? row[lane + 32] : -1e30f;
            float m = fmaxf(v0, v1);
            #pragma unroll
            for (int o = 16; o > 0; o >>= 1)
                m = fmaxf(m, __shfl_xor_sync(0xffffffffu, m, o));
            float s = ((lane < n) ? __expf(v0 - m) : 0.f)
                    + ((lane + 32 < n) ? __expf(v1 - m) : 0.f);
            #pragma unroll
            for (int o = 16; o > 0; o >>= 1)
                s += __shfl_xor_sync(0xffffffffu, s, o);
            if (lane == 0) lse_sh[r] = m + __logf(s);
        }
    }
    __syncthreads();

    // ---- 3. issue emission gathers NOW (labels have arrived) ----
    const float* lpb = log_probs + (size_t)b * S * C + (size_t)ch * CHUNK * C;
    float emis[SUBS];
    #pragma unroll
    for (int i = 0; i < SUBS; i++) {
        int p = i * ROW_THREADS + tid;
        emis[i] = (ys[i] != IGNORE_LBL) ? lpb[(size_t)p * C + ys[i]] : 0.0f;
    }

    // ---- 4. normalized tables (overlaps gather flight) ----
    #pragma unroll
    for (int i = tid; i < L * L; i += ROW_THREADS) {
        int r = i / L, c = i % L;
        trans_sh[i] = A_sh[L + r * LP1 + c] - lse_sh[r];
    }
    if (tid < L) {
        start_sh[tid] = A_sh[tid] - lse_sh[L];
        fin_sh[tid]   = A_sh[L + tid * LP1 + L] - lse_sh[tid];
    }
    __syncthreads();

    // ---- 5. intra-warp transitions + warp-segment endpoints (no emis dep) ----
    double local = 0.0;
    int    cnt   = 0;
    #pragma unroll
    for (int i = 0; i < SUBS; i++) {
        int y = ys[i];
        bool valid = (y != IGNORE_LBL);
        cnt += valid ? 1 : 0;

        unsigned m = __ballot_sync(0xffffffffu, valid);
        unsigned rest = m & (0xFFFFFFFEu << lane);  // valid lanes strictly after me
        int partner = rest ? (__ffs(rest) - 1) : -1;
        int ynext = __shfl_sync(0xffffffffu, y, partner & 31);
        if (valid && partner >= 0)
            local += (double)trans_sh[(y - 1) * L + (ynext - 1)];

        int firstlane = __ffs(m) - 1;
        int lastlane  = 31 - __clz(m | 1u);
        int yf = __shfl_sync(0xffffffffu, y, firstlane & 31);
        int yl = __shfl_sync(0xffffffffu, y, lastlane & 31);
        if (lane == 0) {
            int seg = i * ROW_WARPS + wid;       // segments in position order
            seg_first[seg] = m ? yf : -1;
            seg_last[seg]  = m ? yl : -1;
        }
    }
    __syncthreads();

    // ---- 6. PARALLEL warp-boundary stitching (threads 0..63) ----
    if (tid < 64) {
        bool ne = (seg_first[tid] >= 0);
        unsigned m = __ballot_sync(0xffffffffu, ne);
        if ((tid & 31) == 0) seg_mask[tid >> 5] = m;
    }
    __syncthreads();
    if (tid < NSEG) {
        int s = tid;
        if (seg_first[s] >= 0) {
            unsigned low = (s & 31) ? (seg_mask[s >> 5] & ((1u << (s & 31)) - 1u)) : 0u;
            int pred = -1;
            if (low)                         pred = (s & ~31) + (31 - __clz(low));
            else if (s >= 32 && seg_mask[0]) pred = 31 - __clz(seg_mask[0]);
            if (pred >= 0)
                local += (double)trans_sh[(seg_last[pred] - 1) * L + (seg_first[s] - 1)];
        }
    }
    if (tid == 0) {
        unsigned m0 = seg_mask[0], m1 = seg_mask[1];
        int bf = -1, bl = -1;
        if (m0)      bf = seg_first[__ffs(m0) - 1];
        else if (m1) bf = seg_first[32 + __ffs(m1) - 1];
        if (m1)      bl = seg_last[32 + 31 - __clz(m1)];
        else if (m0) bl = seg_last[31 - __clz(m0)];
        g_first[cid] = bf;
        g_last[cid]  = bl;
    }

    // ---- 7. fold emissions in (gathers have had table+ballot time to land) ----
    #pragma unroll
    for (int i = 0; i < SUBS; i++) local += (double)emis[i];

    // ---- 8. block reduction (double + int) ----
    #pragma unroll
    for (int o = 16; o > 0; o >>= 1) {
        local += __shfl_down_sync(0xffffffffu, local, o);
        cnt   += __shfl_down_sync(0xffffffffu, cnt, o);
    }
    if (lane == 0) { red[wid] = local; redc[wid] = cnt; }
    __syncthreads();
    if (wid == 0) {
        double v = red[lane];
        int    c = redc[lane];
        #pragma unroll
        for (int o = 16; o > 0; o >>= 1) {
            v += __shfl_down_sync(0xffffffffu, v, o);
            c += __shfl_down_sync(0xffffffffu, c, o);
        }
        if (lane == 0) {
            g_partial[cid] = v;
            g_pcount[cid]  = c;
            __threadfence();
            unsigned t = atomicAdd(&g_ticket, 1u);
            is_last = (t == NCHT - 1) ? 1 : 0;
        }
    }
    __syncthreads();

    // ---- 9. last block: stitch chunk boundaries + start/final, finalize ----
    if (is_last) {
        if (tid < B) {
            double s = 0.0; int c = 0, prev = -1, f0 = -1;
            #pragma unroll
            for (int k = 0; k < NCH; k++) {
                int idx = tid * NCH + k;
                s += g_partial[idx];
                c += g_pcount[idx];
                int f = g_first[idx];
                if (f >= 0) {
                    if (prev >= 0) s += (double)trans_sh[(prev - 1) * L + (f - 1)];
                    else           f0 = f;
                    prev = g_last[idx];
                }
            }
            if (f0 >= 0) s += (double)start_sh[f0 - 1] + (double)fin_sh[prev - 1];
            row_sum[tid] = s;
            row_cnt[tid] = c;
        }
        __syncthreads();
        if (wid == 0) {
            double s = row_sum[lane] + row_sum[lane + 32];
            int    c = row_cnt[lane] + row_cnt[lane + 32];
            #pragma unroll
            for (int o = 16; o > 0; o >>= 1) {
                s += __shfl_down_sync(0xffffffffu, s, o);
                c += __shfl_down_sync(0xffffffffu, c, o);
            }
            if (lane == 0) {
                out[0] = (float)(s / (double)c);
                g_ticket = 0;    // reset for graph replay
            }
        }
    }
}

// ---------------------------------------------------------------------------
// Launch
// ---------------------------------------------------------------------------
extern "C" void kernel_launch(void* const* d_in, const int* in_sizes, int n_in,
                              void* d_out, int out_size) {
    const float* log_probs = (const float*)d_in[0];   // (B, S, C) f32
    const float* A_scores  = (const float*)d_in[1];   // (N_ARCS,) f32
    const int*   labels    = (const int*)d_in[2];     // (B, S) i32
    float* out = (float*)d_out;

    crf_fused_kernel<<<NCHT, ROW_THREADS>>>(log_probs, A_scores, labels, out);
}